// round 2
// baseline (speedup 1.0000x reference)
#include <cuda_runtime.h>
#include <math.h>

#define B_ 32
#define T_ 32
#define F_ 64
#define H_ 256
#define N_ 1024
#define A_ 64
#define C_ 192
#define M_ 256
#define NTHREADS 256
#define HSOFF (T_*H_*B_)

// ---------------- persistent state (device globals; no allocation) ----------------
__device__ float g_h[H_*B_];          // h[k*B+b]
__device__ float g_x[T_*F_*B_];       // x[t][f*B+b]
__device__ float g_content[B_*N_*C_]; // 25 MB, content[b][n][c]
__device__ float g_qT[B_*M_];         // q transposed: [b][m]
__device__ float g_beta[B_];
__device__ float g_cand[C_*B_];       // cand[c*B+b]
__device__ float g_gi[3*H_*B_];       // (g*H+hid)*B+b
__device__ float g_gh[3*H_*B_];
__device__ float g_sim[N_*B_];        // sim[n*B+b]
__device__ float g_mx[B_];
__device__ float g_linv[B_];
__device__ float g_reading[B_*M_];    // b-major: reading[b][m]
__device__ unsigned g_bar_arrive = 0;
__device__ volatile unsigned g_bar_gen = 0;

// ---------------- software grid barrier (all blocks co-resident) ----------------
__device__ __forceinline__ void grid_sync(int nblocks) {
    __syncthreads();
    if (threadIdx.x == 0) {
        __threadfence();
        unsigned gen = g_bar_gen;
        unsigned a = atomicAdd(&g_bar_arrive, 1u);
        if (a == (unsigned)nblocks - 1u) {
            g_bar_arrive = 0u;
            __threadfence();
            g_bar_gen = gen + 1u;
        } else {
            while (g_bar_gen == gen) { __nanosleep(64); }
        }
        __threadfence();
    }
    __syncthreads();
}

__device__ __forceinline__ float warp_sum(float v) {
    #pragma unroll
    for (int o = 16; o; o >>= 1) v += __shfl_xor_sync(0xffffffffu, v, o);
    return v;
}
__device__ __forceinline__ float warp_max(float v) {
    #pragma unroll
    for (int o = 16; o; o >>= 1) v = fmaxf(v, __shfl_xor_sync(0xffffffffu, v, o));
    return v;
}

// warp-cooperative: logits + log_softmax for one (t, b)
__device__ __forceinline__ void write_out(const float* __restrict__ Wout,
                                          const float* __restrict__ bo,
                                          float* __restrict__ out,
                                          int tstep, int b, int lane) {
    float logit[10];
    float mx = -1e30f;
    #pragma unroll
    for (int o = 0; o < 10; o++) {
        float s = 0.f;
        #pragma unroll
        for (int j = 0; j < 8; j++) {
            int k = lane + 32*j;
            s += Wout[o*H_ + k] * g_h[k*B_ + b];
        }
        s = warp_sum(s);
        s += bo[o];
        logit[o] = s;
        mx = fmaxf(mx, s);
    }
    float se = 0.f;
    #pragma unroll
    for (int o = 0; o < 10; o++) se += expf(logit[o] - mx);
    float lse = mx + logf(se);
    if (lane == 0) {
        #pragma unroll
        for (int o = 0; o < 10; o++)
            out[HSOFF + (tstep*10 + o)*B_ + b] = logit[o] - lse;
    }
}

__global__ __launch_bounds__(NTHREADS, 2)
void dntm_kernel(const float* __restrict__ batch,
                 const float* __restrict__ Wi,  const float* __restrict__ bi,
                 const float* __restrict__ Wh,  const float* __restrict__ bh,
                 const float* __restrict__ Wm,  const float* __restrict__ bm,
                 const float* __restrict__ Wout,const float* __restrict__ bo,
                 const float* __restrict__ addr,
                 const float* __restrict__ Wq,  const float* __restrict__ bq,
                 const float* __restrict__ u,
                 const float* __restrict__ Wch, const float* __restrict__ Wci,
                 float* __restrict__ out, int nblocks)
{
    const int tid0 = threadIdx.x;
    const int gt   = blockIdx.x * NTHREADS + tid0;
    const int NT   = nblocks * NTHREADS;
    const int lane = tid0 & 31;
    const int wid  = gt >> 5;
    const int nw   = NT >> 5;

    __shared__ float s_red[NTHREADS];

    // ---------------- P0: init state + precompute x_t layout ----------------
    {
        float4 z4 = make_float4(0.f, 0.f, 0.f, 0.f);
        for (int i = gt; i < (B_*N_*C_)/4; i += NT) ((float4*)g_content)[i] = z4;
        for (int i = gt; i < H_*B_; i += NT) g_h[i] = 0.f;
        // xs[t, f', b'] = batch[b, t, f] with (b*F+f) = (f'*B+b')  (raw reshape)
        for (int i = gt; i < T_*F_*B_; i += NT) {
            int t   = i / (F_*B_);
            int lin = i - t*(F_*B_);
            int bb  = lin >> 6;      // / F_
            int ff  = lin & 63;      // % F_
            g_x[i] = batch[bb*(T_*F_) + t*F_ + ff];
        }
    }
    grid_sync(nblocks);

    for (int t = 0; t < T_; t++) {
        const float* xt = g_x + t*F_*B_;

        // ---------------- P1: q, beta, cand, gi, gh (all depend only on h, x_t) ----
        for (int i = gt; i < 63520; i += NT) {
            if (i < 8192) {                       // q[m,b]
                int m = i >> 5, b = i & 31;
                const float* w = Wq + m*H_;
                float s = bq[m];
                #pragma unroll 8
                for (int k = 0; k < H_; k++) s += w[k] * g_h[k*B_ + b];
                g_qT[b*M_ + m] = s;
            } else if (i < 8224) {                // beta[b]
                int b = i - 8192;
                float s = 0.f;
                #pragma unroll 8
                for (int k = 0; k < H_; k++) s += u[k] * g_h[k*B_ + b];
                float sp = (s > 0.f) ? s + log1pf(expf(-s)) : log1pf(expf(s));
                g_beta[b] = sp + 1.f;
            } else if (i < 14368) {               // cand[c,b]
                int ii = i - 8224; int c = ii >> 5, b = ii & 31;
                float s = 0.f;
                #pragma unroll 8
                for (int k = 0; k < H_; k++) s += Wch[c*H_ + k] * g_h[k*B_ + b];
                #pragma unroll 8
                for (int f = 0; f < F_; f++) s += Wci[c*F_ + f] * xt[f*B_ + b];
                g_cand[c*B_ + b] = fmaxf(s, 0.f);
            } else if (i < 38944) {               // gi[g,hid,b]
                int ii = i - 14368; int gi_i = ii >> 5, b = ii & 31;
                const float* w = Wi + gi_i*F_;
                float s = bi[gi_i];
                #pragma unroll 8
                for (int f = 0; f < F_; f++) s += w[f] * xt[f*B_ + b];
                g_gi[gi_i*B_ + b] = s;
            } else {                              // gh[g,hid,b]
                int ii = i - 38944; int gh_i = ii >> 5, b = ii & 31;
                const float* w = Wh + gh_i*H_;
                float s = bh[gh_i];
                #pragma unroll 8
                for (int k = 0; k < H_; k++) s += w[k] * g_h[k*B_ + b];
                g_gh[gh_i*B_ + b] = s;
            }
        }
        grid_sync(nblocks);

        // ---------------- P2: sim[n,b] (1st content pass) + out[t-1] -----------
        if (t > 0 && wid < B_) write_out(Wout, bo, out, t - 1, wid, lane);
        for (int it = wid; it < N_*B_; it += nw) {
            int n = it >> 5, b = it & 31;
            const float* qb   = g_qT + b*M_;
            const float* crow = g_content + (b*N_ + n)*C_;
            const float* arow = addr + n*A_;
            float s = arow[lane]      * qb[lane]
                    + arow[lane + 32] * qb[lane + 32];
            #pragma unroll
            for (int j = 0; j < 6; j++) {
                int c = lane + 32*j;
                s += crow[c] * qb[A_ + c];
            }
            s = warp_sum(s);
            if (lane == 0) g_sim[n*B_ + b] = s;
        }
        grid_sync(nblocks);

        // ---------------- P3: per-b softmax stats; zero reading -----------------
        for (int i = gt; i < B_*M_; i += NT) g_reading[i] = 0.f;
        if (wid < B_) {
            int b = wid;
            float bs = g_beta[b];
            float mx = -1e30f;
            #pragma unroll 4
            for (int j = 0; j < N_/32; j++)
                mx = fmaxf(mx, bs * g_sim[(lane + 32*j)*B_ + b]);
            mx = warp_max(mx);
            float se = 0.f;
            #pragma unroll 4
            for (int j = 0; j < N_/32; j++)
                se += expf(bs * g_sim[(lane + 32*j)*B_ + b] - mx);
            se = warp_sum(se);
            if (lane == 0) { g_mx[b] = mx; g_linv[b] = 1.f / se; }
        }
        grid_sync(nblocks);

        // ---------------- P4: reading (content+addr parts) + content update -----
        {
            int NCH = nblocks >> 5;               // content chunks per b
            if (blockIdx.x < (NCH << 5)) {
                int b  = blockIdx.x & 31;
                int n0 = blockIdx.x >> 5;
                int wl = tid0 >> 5;
                float bs = g_beta[b], mb = g_mx[b], li = g_linv[b];
                float candreg[6];
                #pragma unroll
                for (int j = 0; j < 6; j++) candreg[j] = g_cand[(lane + 32*j)*B_ + b];
                float racc[6] = {0.f,0.f,0.f,0.f,0.f,0.f};
                float a0 = 0.f, a1 = 0.f;
                for (int n = n0 + NCH*wl; n < N_; n += NCH*8) {
                    float wb = expf(bs * g_sim[n*B_ + b] - mb) * li;
                    a0 += wb * addr[n*A_ + lane];
                    a1 += wb * addr[n*A_ + lane + 32];
                    float* crow = g_content + (b*N_ + n)*C_;
                    #pragma unroll
                    for (int j = 0; j < 6; j++) {
                        float v = crow[lane + 32*j];
                        racc[j] += wb * v;
                        crow[lane + 32*j] = v + wb * candreg[j];
                    }
                }
                s_red[tid0] = 0.f;
                __syncthreads();
                atomicAdd(&s_red[lane], a0);
                atomicAdd(&s_red[lane + 32], a1);
                #pragma unroll
                for (int j = 0; j < 6; j++) atomicAdd(&s_red[64 + lane + 32*j], racc[j]);
                __syncthreads();
                // s_red index == m (0..63 addr part, 64..255 content part)
                atomicAdd(&g_reading[b*M_ + tid0], s_red[tid0]);
            }
        }
        grid_sync(nblocks);

        // ---------------- P5: gm + GRU update + hs write -------------------------
        for (int it = wid; it < H_*B_; it += nw) {
            int hid = it >> 5, b = it & 31;
            const float* rb = g_reading + b*M_;
            const float* w0 = Wm + hid*M_;
            const float* w1 = Wm + (H_ + hid)*M_;
            const float* w2 = Wm + (2*H_ + hid)*M_;
            float s0 = 0.f, s1 = 0.f, s2 = 0.f;
            #pragma unroll
            for (int j = 0; j < 8; j++) {
                int m = lane + 32*j;
                float rv = rb[m];
                s0 += w0[m]*rv; s1 += w1[m]*rv; s2 += w2[m]*rv;
            }
            s0 = warp_sum(s0); s1 = warp_sum(s1); s2 = warp_sum(s2);
            if (lane == 0) {
                int gb = hid*B_ + b;
                float gm0 = s0 + bm[hid];
                float gm1 = s1 + bm[H_ + hid];
                float gm2 = s2 + bm[2*H_ + hid];
                float r  = 1.f / (1.f + expf(-(g_gi[gb] + g_gh[gb] + gm0)));
                float z  = 1.f / (1.f + expf(-(g_gi[H_*B_ + gb] + g_gh[H_*B_ + gb] + gm1)));
                float nn = tanhf(g_gi[2*H_*B_ + gb] + gm2 + r * g_gh[2*H_*B_ + gb]);
                float hn = (1.f - z)*nn + z*g_h[gb];
                g_h[gb] = hn;
                out[t*H_*B_ + gb] = hn;
            }
        }
        grid_sync(nblocks);
    }

    // final timestep's output head (uses h_T, complete after last barrier)
    if (wid < B_) write_out(Wout, bo, out, T_ - 1, wid, lane);
}

extern "C" void kernel_launch(void* const* d_in, const int* in_sizes, int n_in,
                              void* d_out, int out_size) {
    (void)in_sizes; (void)n_in; (void)out_size;
    const float* batch = (const float*)d_in[0];
    const float* Wi    = (const float*)d_in[1];
    const float* bi    = (const float*)d_in[2];
    const float* Wh    = (const float*)d_in[3];
    const float* bh    = (const float*)d_in[4];
    const float* Wm    = (const float*)d_in[5];
    const float* bm    = (const float*)d_in[6];
    const float* Wout  = (const float*)d_in[7];
    const float* bo    = (const float*)d_in[8];
    const float* addr  = (const float*)d_in[9];
    const float* Wq    = (const float*)d_in[10];
    const float* bq    = (const float*)d_in[11];
    const float* u     = (const float*)d_in[12];
    const float* Wch   = (const float*)d_in[13];
    const float* Wci   = (const float*)d_in[14];
    float* out = (float*)d_out;

    int dev = 0;
    cudaGetDevice(&dev);
    int sms = 148;
    cudaDeviceGetAttribute(&sms, cudaDevAttrMultiProcessorCount, dev);
    int occ = 1;
    cudaOccupancyMaxActiveBlocksPerMultiprocessor(&occ, dntm_kernel, NTHREADS, 0);
    if (occ < 1) occ = 1;
    if (occ > 2) occ = 2;              // co-residency guaranteed; barrier cost bounded
    int grid = sms * occ;

    dntm_kernel<<<grid, NTHREADS>>>(batch, Wi, bi, Wh, bh, Wm, bm, Wout, bo,
                                    addr, Wq, bq, u, Wch, Wci, out, grid);
}

// round 3
// speedup vs baseline: 1.1167x; 1.1167x over previous
#include <cuda_runtime.h>
#include <math.h>

#define B_ 32
#define T_ 32
#define F_ 64
#define H_ 256
#define N_ 1024
#define A_ 64
#define C_ 192
#define M_ 256
#define NTHREADS 256
#define HSOFF (T_*H_*B_)

// ---------------- persistent state (device globals; no allocation) ----------------
__device__ float g_h[H_*B_];          // h[k*B+b]
__device__ float g_x[T_*F_*B_];       // x[t][f*B+b]
__device__ float g_content[B_*N_*C_]; // 25 MB, content[b][n][c]
__device__ float g_qT[B_*M_];         // q transposed: [b][m]
__device__ float g_beta[B_];
__device__ float g_cand[C_*B_];       // cand[c*B+b]
__device__ float g_gi[3*H_*B_];       // (g*H+hid)*B+b
__device__ float g_gh[3*H_*B_];
__device__ float g_sim[N_*B_];        // sim[n*B+b]
__device__ float g_reading[B_*M_];    // b-major: reading[b][m]
__device__ unsigned g_leaf[16];
__device__ unsigned g_root = 0;
__device__ volatile unsigned g_bar_gen = 0;

// ---------------- software grid barrier, tree arrivals (all blocks co-resident) ---
__device__ __forceinline__ void grid_sync(int nblocks) {
    __syncthreads();
    if (threadIdx.x == 0) {
        __threadfence();
        unsigned gen = g_bar_gen;
        int leaf = blockIdx.x & 15;
        unsigned lsz = (unsigned)(nblocks >> 4) + ((leaf < (nblocks & 15)) ? 1u : 0u);
        if (atomicAdd(&g_leaf[leaf], 1u) == lsz - 1u) {
            atomicExch(&g_leaf[leaf], 0u);           // reset before root arrival
            if (atomicAdd(&g_root, 1u) == 15u) {
                atomicExch(&g_root, 0u);
                __threadfence();
                g_bar_gen = gen + 1u;                // release
            }
        }
        while (g_bar_gen == gen) { __nanosleep(32); }
        __threadfence();
    }
    __syncthreads();
}

__device__ __forceinline__ float warp_sum(float v) {
    #pragma unroll
    for (int o = 16; o; o >>= 1) v += __shfl_xor_sync(0xffffffffu, v, o);
    return v;
}
__device__ __forceinline__ float warp_max(float v) {
    #pragma unroll
    for (int o = 16; o; o >>= 1) v = fmaxf(v, __shfl_xor_sync(0xffffffffu, v, o));
    return v;
}

// warp-cooperative: logits + log_softmax for one (t, b)
__device__ __forceinline__ void write_out(const float* __restrict__ Wout,
                                          const float* __restrict__ bo,
                                          float* __restrict__ out,
                                          int tstep, int b, int lane) {
    float logit[10];
    float mx = -1e30f;
    #pragma unroll
    for (int o = 0; o < 10; o++) {
        float s = 0.f;
        #pragma unroll
        for (int j = 0; j < 8; j++) {
            int k = lane + 32*j;
            s += Wout[o*H_ + k] * g_h[k*B_ + b];
        }
        s = warp_sum(s);
        s += bo[o];
        logit[o] = s;
        mx = fmaxf(mx, s);
    }
    float se = 0.f;
    #pragma unroll
    for (int o = 0; o < 10; o++) se += expf(logit[o] - mx);
    float lse = mx + logf(se);
    if (lane == 0) {
        #pragma unroll
        for (int o = 0; o < 10; o++)
            out[HSOFF + (tstep*10 + o)*B_ + b] = logit[o] - lse;
    }
}

__global__ __launch_bounds__(NTHREADS, 2)
void dntm_kernel(const float* __restrict__ batch,
                 const float* __restrict__ Wi,  const float* __restrict__ bi,
                 const float* __restrict__ Wh,  const float* __restrict__ bh,
                 const float* __restrict__ Wm,  const float* __restrict__ bm,
                 const float* __restrict__ Wout,const float* __restrict__ bo,
                 const float* __restrict__ addr,
                 const float* __restrict__ Wq,  const float* __restrict__ bq,
                 const float* __restrict__ u,
                 const float* __restrict__ Wch, const float* __restrict__ Wci,
                 float* __restrict__ out, int nblocks)
{
    const int tid0 = threadIdx.x;
    const int gt   = blockIdx.x * NTHREADS + tid0;
    const int NT   = nblocks * NTHREADS;
    const int lane = tid0 & 31;
    const int wid  = gt >> 5;
    const int nw   = NT >> 5;

    __shared__ float s_red[NTHREADS];

    // ---------------- P0: init state + precompute x_t layout ----------------
    {
        float4 z4 = make_float4(0.f, 0.f, 0.f, 0.f);
        for (int i = gt; i < (B_*N_*C_)/4; i += NT) ((float4*)g_content)[i] = z4;
        for (int i = gt; i < H_*B_; i += NT) g_h[i] = 0.f;
        // xs[t, f', b'] = batch[b, t, f] with (b*F+f) = (f'*B+b')  (raw reshape)
        for (int i = gt; i < T_*F_*B_; i += NT) {
            int t   = i / (F_*B_);
            int lin = i - t*(F_*B_);
            int bb  = lin >> 6;      // / F_
            int ff  = lin & 63;      // % F_
            g_x[i] = batch[bb*(T_*F_) + t*F_ + ff];
        }
    }
    grid_sync(nblocks);

    for (int t = 0; t < T_; t++) {
        const float* xt = g_x + t*F_*B_;

        // ------ P1: q, beta, cand, gi, gh (depend only on h, x_t); zero reading ----
        for (int i = gt; i < 71712; i += NT) {
            if (i < 8192) {                       // q[m,b]
                int m = i >> 5, b = i & 31;
                const float* w = Wq + m*H_;
                float s = bq[m];
                #pragma unroll 8
                for (int k = 0; k < H_; k++) s += w[k] * g_h[k*B_ + b];
                g_qT[b*M_ + m] = s;
            } else if (i < 8224) {                // beta[b]
                int b = i - 8192;
                float s = 0.f;
                #pragma unroll 8
                for (int k = 0; k < H_; k++) s += u[k] * g_h[k*B_ + b];
                float sp = (s > 0.f) ? s + log1pf(expf(-s)) : log1pf(expf(s));
                g_beta[b] = sp + 1.f;
            } else if (i < 14368) {               // cand[c,b]
                int ii = i - 8224; int c = ii >> 5, b = ii & 31;
                float s = 0.f;
                #pragma unroll 8
                for (int k = 0; k < H_; k++) s += Wch[c*H_ + k] * g_h[k*B_ + b];
                #pragma unroll 8
                for (int f = 0; f < F_; f++) s += Wci[c*F_ + f] * xt[f*B_ + b];
                g_cand[c*B_ + b] = fmaxf(s, 0.f);
            } else if (i < 38944) {               // gi[g,hid,b]
                int ii = i - 14368; int gi_i = ii >> 5, b = ii & 31;
                const float* w = Wi + gi_i*F_;
                float s = bi[gi_i];
                #pragma unroll 8
                for (int f = 0; f < F_; f++) s += w[f] * xt[f*B_ + b];
                g_gi[gi_i*B_ + b] = s;
            } else if (i < 63520) {               // gh[g,hid,b]
                int ii = i - 38944; int gh_i = ii >> 5, b = ii & 31;
                const float* w = Wh + gh_i*H_;
                float s = bh[gh_i];
                #pragma unroll 8
                for (int k = 0; k < H_; k++) s += w[k] * g_h[k*B_ + b];
                g_gh[gh_i*B_ + b] = s;
            } else {                              // zero g_reading (consumed last P5)
                g_reading[i - 63520] = 0.f;
            }
        }
        grid_sync(nblocks);

        // ---------------- P2: sim[n,b] (1st content pass) + out[t-1] -----------
        if (t > 0 && wid < B_) write_out(Wout, bo, out, t - 1, wid, lane);
        for (int it = wid; it < N_*B_; it += nw) {
            int n = it >> 5, b = it & 31;
            const float* qb   = g_qT + b*M_;
            const float* crow = g_content + (b*N_ + n)*C_;
            const float* arow = addr + n*A_;
            float s = arow[lane]      * qb[lane]
                    + arow[lane + 32] * qb[lane + 32];
            #pragma unroll
            for (int j = 0; j < 6; j++) {
                int c = lane + 32*j;
                s += crow[c] * qb[A_ + c];
            }
            s = warp_sum(s);
            if (lane == 0) g_sim[n*B_ + b] = s;
        }
        grid_sync(nblocks);

        // ------ P4: per-block softmax stats, then reading + content update ------
        {
            int NCH = nblocks >> 5;               // content chunks per b
            if (blockIdx.x < (NCH << 5)) {
                int b  = blockIdx.x & 31;
                int n0 = blockIdx.x >> 5;
                int wl = tid0 >> 5;
                float bs = g_beta[b];

                // softmax stats over bs*sim[:,b], block-local (replaces old P3)
                float v0 = bs * g_sim[(tid0      )*B_ + b];
                float v1 = bs * g_sim[(tid0 + 256)*B_ + b];
                float v2 = bs * g_sim[(tid0 + 512)*B_ + b];
                float v3 = bs * g_sim[(tid0 + 768)*B_ + b];
                float m = fmaxf(fmaxf(v0, v1), fmaxf(v2, v3));
                m = warp_max(m);
                if (lane == 0) s_red[wl] = m;
                __syncthreads();
                float mb = s_red[0];
                #pragma unroll
                for (int w = 1; w < 8; w++) mb = fmaxf(mb, s_red[w]);
                float e = expf(v0 - mb) + expf(v1 - mb) + expf(v2 - mb) + expf(v3 - mb);
                e = warp_sum(e);
                __syncthreads();
                if (lane == 0) s_red[wl] = e;
                __syncthreads();
                float ss = 0.f;
                #pragma unroll
                for (int w = 0; w < 8; w++) ss += s_red[w];
                float li = 1.f / ss;
                __syncthreads();

                float candreg[6];
                #pragma unroll
                for (int j = 0; j < 6; j++) candreg[j] = g_cand[(lane + 32*j)*B_ + b];
                float racc[6] = {0.f,0.f,0.f,0.f,0.f,0.f};
                float a0 = 0.f, a1 = 0.f;
                for (int n = n0 + NCH*wl; n < N_; n += NCH*8) {
                    float wb = expf(bs * g_sim[n*B_ + b] - mb) * li;
                    a0 += wb * addr[n*A_ + lane];
                    a1 += wb * addr[n*A_ + lane + 32];
                    float* crow = g_content + (b*N_ + n)*C_;
                    #pragma unroll
                    for (int j = 0; j < 6; j++) {
                        float v = crow[lane + 32*j];
                        racc[j] += wb * v;
                        crow[lane + 32*j] = v + wb * candreg[j];
                    }
                }
                s_red[tid0] = 0.f;
                __syncthreads();
                atomicAdd(&s_red[lane], a0);
                atomicAdd(&s_red[lane + 32], a1);
                #pragma unroll
                for (int j = 0; j < 6; j++) atomicAdd(&s_red[64 + lane + 32*j], racc[j]);
                __syncthreads();
                // s_red index == m (0..63 addr part, 64..255 content part)
                atomicAdd(&g_reading[b*M_ + tid0], s_red[tid0]);
            }
        }
        grid_sync(nblocks);

        // ---------------- P5: gm + GRU update + hs write -------------------------
        for (int it = wid; it < H_*B_; it += nw) {
            int hid = it >> 5, b = it & 31;
            const float* rb = g_reading + b*M_;
            const float* w0 = Wm + hid*M_;
            const float* w1 = Wm + (H_ + hid)*M_;
            const float* w2 = Wm + (2*H_ + hid)*M_;
            float s0 = 0.f, s1 = 0.f, s2 = 0.f;
            #pragma unroll
            for (int j = 0; j < 8; j++) {
                int m = lane + 32*j;
                float rv = rb[m];
                s0 += w0[m]*rv; s1 += w1[m]*rv; s2 += w2[m]*rv;
            }
            s0 = warp_sum(s0); s1 = warp_sum(s1); s2 = warp_sum(s2);
            if (lane == 0) {
                int gb = hid*B_ + b;
                float gm0 = s0 + bm[hid];
                float gm1 = s1 + bm[H_ + hid];
                float gm2 = s2 + bm[2*H_ + hid];
                float r  = 1.f / (1.f + expf(-(g_gi[gb] + g_gh[gb] + gm0)));
                float z  = 1.f / (1.f + expf(-(g_gi[H_*B_ + gb] + g_gh[H_*B_ + gb] + gm1)));
                float nn = tanhf(g_gi[2*H_*B_ + gb] + gm2 + r * g_gh[2*H_*B_ + gb]);
                float hn = (1.f - z)*nn + z*g_h[gb];
                g_h[gb] = hn;
                out[t*H_*B_ + gb] = hn;
            }
        }
        grid_sync(nblocks);
    }

    // final timestep's output head (uses h_T, complete after last barrier)
    if (wid < B_) write_out(Wout, bo, out, T_ - 1, wid, lane);
}

extern "C" void kernel_launch(void* const* d_in, const int* in_sizes, int n_in,
                              void* d_out, int out_size) {
    (void)in_sizes; (void)n_in; (void)out_size;
    const float* batch = (const float*)d_in[0];
    const float* Wi    = (const float*)d_in[1];
    const float* bi    = (const float*)d_in[2];
    const float* Wh    = (const float*)d_in[3];
    const float* bh    = (const float*)d_in[4];
    const float* Wm    = (const float*)d_in[5];
    const float* bm    = (const float*)d_in[6];
    const float* Wout  = (const float*)d_in[7];
    const float* bo    = (const float*)d_in[8];
    const float* addr  = (const float*)d_in[9];
    const float* Wq    = (const float*)d_in[10];
    const float* bq    = (const float*)d_in[11];
    const float* u     = (const float*)d_in[12];
    const float* Wch   = (const float*)d_in[13];
    const float* Wci   = (const float*)d_in[14];
    float* out = (float*)d_out;

    int dev = 0;
    cudaGetDevice(&dev);
    int sms = 148;
    cudaDeviceGetAttribute(&sms, cudaDevAttrMultiProcessorCount, dev);
    int occ = 1;
    cudaOccupancyMaxActiveBlocksPerMultiprocessor(&occ, dntm_kernel, NTHREADS, 0);
    if (occ < 1) occ = 1;
    if (occ > 2) occ = 2;              // co-residency guaranteed; barrier cost bounded
    int grid = sms * occ;

    dntm_kernel<<<grid, NTHREADS>>>(batch, Wi, bi, Wh, bh, Wm, bm, Wout, bo,
                                    addr, Wq, bq, u, Wch, Wci, out, grid);
}

// round 4
// speedup vs baseline: 1.2660x; 1.1337x over previous
#include <cuda_runtime.h>
#include <math.h>

#define B_ 32
#define T_ 32
#define F_ 64
#define H_ 256
#define N_ 1024
#define A_ 64
#define C_ 192
#define M_ 256
#define NTHREADS 256
#define HSOFF (T_*H_*B_)

// ---------------- persistent state (device globals; no allocation) ----------------
__device__ float g_h[H_*B_];          // h[k*B+b]
__device__ float g_x[T_*F_*B_];       // x[t][f*B+b]
__device__ float g_content[B_*N_*C_]; // 25 MB, content[b][n][c]
__device__ float g_qT[B_*M_];         // q transposed: [b][m]
__device__ float g_beta[B_];
__device__ float g_cand[C_*B_];       // cand[c*B+b]
__device__ float g_gi[3*H_*B_];       // (g*H+hid)*B+b
__device__ float g_gh[3*H_*B_];
__device__ float g_simT[B_*N_];       // beta*sim, b-major: [b][n]  (coalesced in P4)
__device__ float g_reading[B_*M_];    // b-major: reading[b][m]
__device__ unsigned g_leaf[16];
__device__ unsigned g_root = 0;
__device__ volatile unsigned g_bar_gen = 0;

// ---------------- software grid barrier, tree arrivals (all blocks co-resident) ---
__device__ __forceinline__ void grid_sync(int nblocks) {
    __syncthreads();
    if (threadIdx.x == 0) {
        __threadfence();
        unsigned gen = g_bar_gen;
        int leaf = blockIdx.x & 15;
        unsigned lsz = (unsigned)(nblocks >> 4) + ((leaf < (nblocks & 15)) ? 1u : 0u);
        if (atomicAdd(&g_leaf[leaf], 1u) == lsz - 1u) {
            atomicExch(&g_leaf[leaf], 0u);           // reset before root arrival
            if (atomicAdd(&g_root, 1u) == 15u) {
                atomicExch(&g_root, 0u);
                __threadfence();
                g_bar_gen = gen + 1u;                // release
            }
        }
        while (g_bar_gen == gen) { __nanosleep(32); }
        __threadfence();
    }
    __syncthreads();
}

__device__ __forceinline__ float warp_sum(float v) {
    #pragma unroll
    for (int o = 16; o; o >>= 1) v += __shfl_xor_sync(0xffffffffu, v, o);
    return v;
}
__device__ __forceinline__ float warp_max(float v) {
    #pragma unroll
    for (int o = 16; o; o >>= 1) v = fmaxf(v, __shfl_xor_sync(0xffffffffu, v, o));
    return v;
}

// warp-cooperative: logits + log_softmax for one (t, b)
__device__ __forceinline__ void write_out(const float* __restrict__ Wout,
                                          const float* __restrict__ bo,
                                          float* __restrict__ out,
                                          int tstep, int b, int lane) {
    float logit[10];
    float mx = -1e30f;
    #pragma unroll
    for (int o = 0; o < 10; o++) {
        float s = 0.f;
        #pragma unroll
        for (int j = 0; j < 8; j++) {
            int k = lane + 32*j;
            s += Wout[o*H_ + k] * g_h[k*B_ + b];
        }
        s = warp_sum(s);
        s += bo[o];
        logit[o] = s;
        mx = fmaxf(mx, s);
    }
    float se = 0.f;
    #pragma unroll
    for (int o = 0; o < 10; o++) se += expf(logit[o] - mx);
    float lse = mx + logf(se);
    if (lane == 0) {
        #pragma unroll
        for (int o = 0; o < 10; o++)
            out[HSOFF + (tstep*10 + o)*B_ + b] = logit[o] - lse;
    }
}

__global__ __launch_bounds__(NTHREADS, 4)
void dntm_kernel(const float* __restrict__ batch,
                 const float* __restrict__ Wi,  const float* __restrict__ bi,
                 const float* __restrict__ Wh,  const float* __restrict__ bh,
                 const float* __restrict__ Wm,  const float* __restrict__ bm,
                 const float* __restrict__ Wout,const float* __restrict__ bo,
                 const float* __restrict__ addr,
                 const float* __restrict__ Wq,  const float* __restrict__ bq,
                 const float* __restrict__ u,
                 const float* __restrict__ Wch, const float* __restrict__ Wci,
                 float* __restrict__ out, int nblocks)
{
    const int tid0 = threadIdx.x;
    const int gt   = blockIdx.x * NTHREADS + tid0;
    const int NT   = nblocks * NTHREADS;
    const int lane = tid0 & 31;
    const int wid  = gt >> 5;
    const int nw   = NT >> 5;

    __shared__ float s_red[NTHREADS];

    // ---------------- P0: init state + precompute x_t layout ----------------
    {
        float4 z4 = make_float4(0.f, 0.f, 0.f, 0.f);
        for (int i = gt; i < (B_*N_*C_)/4; i += NT) ((float4*)g_content)[i] = z4;
        for (int i = gt; i < H_*B_; i += NT) g_h[i] = 0.f;
        // xs[t, f', b'] = batch[b, t, f] with (b*F+f) = (f'*B+b')  (raw reshape)
        for (int i = gt; i < T_*F_*B_; i += NT) {
            int t   = i / (F_*B_);
            int lin = i - t*(F_*B_);
            int bb  = lin >> 6;      // / F_
            int ff  = lin & 63;      // % F_
            g_x[i] = batch[bb*(T_*F_) + t*F_ + ff];
        }
    }
    grid_sync(nblocks);

    for (int t = 0; t < T_; t++) {
        const float* xt = g_x + t*F_*B_;

        // ------ P1: q, beta, cand, gi, gh (depend only on h, x_t); zero reading ----
        for (int i = gt; i < 71712; i += NT) {
            if (i < 8192) {                       // q[m,b]
                int m = i >> 5, b = i & 31;
                const float* w = Wq + m*H_;
                float s = bq[m];
                #pragma unroll 8
                for (int k = 0; k < H_; k++) s += w[k] * g_h[k*B_ + b];
                g_qT[b*M_ + m] = s;
            } else if (i < 8224) {                // beta[b]
                int b = i - 8192;
                float s = 0.f;
                #pragma unroll 8
                for (int k = 0; k < H_; k++) s += u[k] * g_h[k*B_ + b];
                float sp = (s > 0.f) ? s + log1pf(expf(-s)) : log1pf(expf(s));
                g_beta[b] = sp + 1.f;
            } else if (i < 14368) {               // cand[c,b]
                int ii = i - 8224; int c = ii >> 5, b = ii & 31;
                float s = 0.f;
                #pragma unroll 8
                for (int k = 0; k < H_; k++) s += Wch[c*H_ + k] * g_h[k*B_ + b];
                #pragma unroll 8
                for (int f = 0; f < F_; f++) s += Wci[c*F_ + f] * xt[f*B_ + b];
                g_cand[c*B_ + b] = fmaxf(s, 0.f);
            } else if (i < 38944) {               // gi[g,hid,b]
                int ii = i - 14368; int gi_i = ii >> 5, b = ii & 31;
                const float* w = Wi + gi_i*F_;
                float s = bi[gi_i];
                #pragma unroll 8
                for (int f = 0; f < F_; f++) s += w[f] * xt[f*B_ + b];
                g_gi[gi_i*B_ + b] = s;
            } else if (i < 63520) {               // gh[g,hid,b]
                int ii = i - 38944; int gh_i = ii >> 5, b = ii & 31;
                const float* w = Wh + gh_i*H_;
                float s = bh[gh_i];
                #pragma unroll 8
                for (int k = 0; k < H_; k++) s += w[k] * g_h[k*B_ + b];
                g_gh[gh_i*B_ + b] = s;
            } else {                              // zero g_reading (consumed last P5)
                g_reading[i - 63520] = 0.f;
            }
        }
        grid_sync(nblocks);

        // ---------------- P2: beta*sim -> g_simT[b][n] + out[t-1] ---------------
        if (t > 0 && wid < B_) write_out(Wout, bo, out, t - 1, wid, lane);
        for (int it = wid; it < N_*B_; it += nw) {
            int n = it >> 5, b = it & 31;
            const float* qb   = g_qT + b*M_;
            const float* crow = g_content + (b*N_ + n)*C_;
            const float* arow = addr + n*A_;
            float s = arow[lane]      * qb[lane]
                    + arow[lane + 32] * qb[lane + 32];
            #pragma unroll
            for (int j = 0; j < 6; j++) {
                int c = lane + 32*j;
                s += crow[c] * qb[A_ + c];
            }
            s = warp_sum(s);
            if (lane == 0) g_simT[b*N_ + n] = g_beta[b] * s;
        }
        grid_sync(nblocks);

        // ------ P4: per-block softmax stats, then reading + content update ------
        {
            int NCH = nblocks >> 5;               // content chunks per b
            if (blockIdx.x < (NCH << 5)) {
                int b  = blockIdx.x & 31;
                int n0 = blockIdx.x >> 5;
                int wl = tid0 >> 5;
                const float* simb = g_simT + b*N_;

                // softmax stats over simb[0..N), coalesced loads
                float v0 = simb[tid0      ];
                float v1 = simb[tid0 + 256];
                float v2 = simb[tid0 + 512];
                float v3 = simb[tid0 + 768];
                float m = fmaxf(fmaxf(v0, v1), fmaxf(v2, v3));
                m = warp_max(m);
                if (lane == 0) s_red[wl] = m;
                __syncthreads();
                float mb = s_red[0];
                #pragma unroll
                for (int w = 1; w < 8; w++) mb = fmaxf(mb, s_red[w]);
                float e = expf(v0 - mb) + expf(v1 - mb) + expf(v2 - mb) + expf(v3 - mb);
                e = warp_sum(e);
                __syncthreads();
                if (lane == 0) s_red[wl] = e;
                __syncthreads();
                float ss = 0.f;
                #pragma unroll
                for (int w = 0; w < 8; w++) ss += s_red[w];
                float li = 1.f / ss;
                __syncthreads();

                float candreg[6];
                #pragma unroll
                for (int j = 0; j < 6; j++) candreg[j] = g_cand[(lane + 32*j)*B_ + b];
                float racc[6] = {0.f,0.f,0.f,0.f,0.f,0.f};
                float a0 = 0.f, a1 = 0.f;
                for (int n = n0 + NCH*wl; n < N_; n += NCH*8) {
                    float wb = expf(simb[n] - mb) * li;
                    a0 += wb * addr[n*A_ + lane];
                    a1 += wb * addr[n*A_ + lane + 32];
                    float* crow = g_content + (b*N_ + n)*C_;
                    #pragma unroll
                    for (int j = 0; j < 6; j++) {
                        float v = crow[lane + 32*j];
                        racc[j] += wb * v;
                        crow[lane + 32*j] = v + wb * candreg[j];
                    }
                }
                s_red[tid0] = 0.f;
                __syncthreads();
                atomicAdd(&s_red[lane], a0);
                atomicAdd(&s_red[lane + 32], a1);
                #pragma unroll
                for (int j = 0; j < 6; j++) atomicAdd(&s_red[64 + lane + 32*j], racc[j]);
                __syncthreads();
                // s_red index == m (0..63 addr part, 64..255 content part)
                atomicAdd(&g_reading[b*M_ + tid0], s_red[tid0]);
            }
        }
        grid_sync(nblocks);

        // ---------------- P5: gm + GRU update + hs write -------------------------
        for (int it = wid; it < H_*B_; it += nw) {
            int hid = it >> 5, b = it & 31;
            const float* rb = g_reading + b*M_;
            const float* w0 = Wm + hid*M_;
            const float* w1 = Wm + (H_ + hid)*M_;
            const float* w2 = Wm + (2*H_ + hid)*M_;
            float s0 = 0.f, s1 = 0.f, s2 = 0.f;
            #pragma unroll
            for (int j = 0; j < 8; j++) {
                int m = lane + 32*j;
                float rv = rb[m];
                s0 += w0[m]*rv; s1 += w1[m]*rv; s2 += w2[m]*rv;
            }
            s0 = warp_sum(s0); s1 = warp_sum(s1); s2 = warp_sum(s2);
            if (lane == 0) {
                int gb = hid*B_ + b;
                float gm0 = s0 + bm[hid];
                float gm1 = s1 + bm[H_ + hid];
                float gm2 = s2 + bm[2*H_ + hid];
                float r  = 1.f / (1.f + expf(-(g_gi[gb] + g_gh[gb] + gm0)));
                float z  = 1.f / (1.f + expf(-(g_gi[H_*B_ + gb] + g_gh[H_*B_ + gb] + gm1)));
                float nn = tanhf(g_gi[2*H_*B_ + gb] + gm2 + r * g_gh[2*H_*B_ + gb]);
                float hn = (1.f - z)*nn + z*g_h[gb];
                g_h[gb] = hn;
                out[t*H_*B_ + gb] = hn;
            }
        }
        grid_sync(nblocks);
    }

    // final timestep's output head (uses h_T, complete after last barrier)
    if (wid < B_) write_out(Wout, bo, out, T_ - 1, wid, lane);
}

extern "C" void kernel_launch(void* const* d_in, const int* in_sizes, int n_in,
                              void* d_out, int out_size) {
    (void)in_sizes; (void)n_in; (void)out_size;
    const float* batch = (const float*)d_in[0];
    const float* Wi    = (const float*)d_in[1];
    const float* bi    = (const float*)d_in[2];
    const float* Wh    = (const float*)d_in[3];
    const float* bh    = (const float*)d_in[4];
    const float* Wm    = (const float*)d_in[5];
    const float* bm    = (const float*)d_in[6];
    const float* Wout  = (const float*)d_in[7];
    const float* bo    = (const float*)d_in[8];
    const float* addr  = (const float*)d_in[9];
    const float* Wq    = (const float*)d_in[10];
    const float* bq    = (const float*)d_in[11];
    const float* u     = (const float*)d_in[12];
    const float* Wch   = (const float*)d_in[13];
    const float* Wci   = (const float*)d_in[14];
    float* out = (float*)d_out;

    int dev = 0;
    cudaGetDevice(&dev);
    int sms = 148;
    cudaDeviceGetAttribute(&sms, cudaDevAttrMultiProcessorCount, dev);
    int occ = 1;
    cudaOccupancyMaxActiveBlocksPerMultiprocessor(&occ, dntm_kernel, NTHREADS, 0);
    if (occ < 1) occ = 1;
    if (occ > 4) occ = 4;              // co-residency guaranteed
    int grid = sms * occ;

    dntm_kernel<<<grid, NTHREADS>>>(batch, Wi, bi, Wh, bh, Wm, bm, Wout, bo,
                                    addr, Wq, bq, u, Wch, Wci, out, grid);
}